// round 17
// baseline (speedup 1.0000x reference)
#include <cuda_runtime.h>
#include <cstdint>

#define TPB 256

// ---------------- smem layout (bytes) ----------------
// A slots: 64 rows x 36 floats (K=32 + 4 pad)  -> 9216 B each
// B slots: 256 rows x 36 floats                -> 36864 B each
#define AS 36
#define BSTR 36
#define ASLOT(s) ((s) * 9216)
#define BSLOT(s) (18432 + (s) * 36864)
#define RED_OFF 92160
#define SMEM_TOTAL 93184            /* x2 CTAs = 186368 <= 227KB carveout */

// gmem scratch: attended / h_tilde (write->read within the same CTA only)
__device__ float g_att[(size_t)65536 * 256];
// pre-tf32-rounded weights: [Wa, Ua, Wh, Uh, Wz, Uz]
__device__ float g_w[6 * 65536];

__device__ __forceinline__ uint32_t cvt_tf32(float f) {
    uint32_t u;
    asm("cvt.rna.tf32.f32 %0, %1;" : "=r"(u) : "f"(f));
    return u;
}

__device__ __forceinline__ void mma8(float* d, const uint32_t* a, const uint32_t* b) {
    asm volatile(
        "mma.sync.aligned.m16n8k8.row.col.f32.tf32.tf32.f32 "
        "{%0,%1,%2,%3}, {%4,%5,%6,%7}, {%8,%9}, {%0,%1,%2,%3};"
        : "+f"(d[0]), "+f"(d[1]), "+f"(d[2]), "+f"(d[3])
        : "r"(a[0]), "r"(a[1]), "r"(a[2]), "r"(a[3]), "r"(b[0]), "r"(b[1]));
}

__device__ __forceinline__ float fast_tanh(float v) {
    float e = __expf(-2.f * fabsf(v));
    float t = __fdividef(1.f - e, 1.f + e);
    return copysignf(t, v);
}
__device__ __forceinline__ float fast_sig(float v) {
    return __fdividef(1.f, 1.f + __expf(-v));
}

__device__ __forceinline__ void sts_quad(char* sm, int off_bytes, float4 v) {
    uint4 u = { cvt_tf32(v.x), cvt_tf32(v.y), cvt_tf32(v.z), cvt_tf32(v.w) };
    *reinterpret_cast<uint4*>(sm + off_bytes) = u;
}

__device__ __forceinline__ void cp16(uint32_t dst, const float* src) {
    asm volatile("cp.async.ca.shared.global [%0], [%1], 16;"
                 :: "r"(dst), "l"(__cvta_generic_to_global(src)) : "memory");
}
#define CP_COMMIT() asm volatile("cp.async.commit_group;" ::: "memory")
#define CP_WAIT0()  asm volatile("cp.async.wait_group 0;" ::: "memory")

// One MMA step over k8 index t on the slot pointed to by Asp/Bsp.
__device__ __forceinline__ void mma_step(
    const uint32_t* Asp, const uint32_t* Bsp, float acc[2][8][4],
    int t, int g, int c, int rbase, int nw)
{
    const int k = t * 8 + c;
    uint32_t afr[2][4];
    #pragma unroll
    for (int i = 0; i < 2; i++) {
        const int r0 = rbase + i * 16;
        afr[i][0] = Asp[r0 * AS + k];
        afr[i][1] = Asp[(r0 + 8) * AS + k];
        afr[i][2] = Asp[r0 * AS + k + 4];
        afr[i][3] = Asp[(r0 + 8) * AS + k + 4];
    }
    #pragma unroll
    for (int j = 0; j < 8; j++) {
        const int n = nw * 64 + j * 8 + g;
        uint32_t bf[2] = { Bsp[n * BSTR + k], Bsp[n * BSTR + k + 4] };
        mma8(acc[0][j], afr[0], bf);
        mma8(acc[1][j], afr[1], bf);
    }
}

// One full phase: acc += A0[64x256] @ B0^T + A1[64x256] @ B1^T.
// B (pre-rounded weights) streams via cp.async; A streams via LDG+cvt+STS.
// 16 chunks of K=32, double-buffered, exactly 1 __syncthreads per chunk.
__device__ __forceinline__ void run_phase(
    char* sm, uint32_t sbase,
    const float* __restrict__ A0, const float* __restrict__ A1,
    const float* __restrict__ B0, const float* __restrict__ B1,
    float acc[2][8][4], int tid, int g, int c, int rbase, int nw)
{
    const int arow = tid >> 2, aseg = (tid & 3) * 8;
    const int brow = tid;
    const uint32_t bofs = (uint32_t)brow * (BSTR * 4);

    // prologue: issue chunk 0
    {
        const float* bs = B0 + (size_t)brow * 256;
        const uint32_t bd = sbase + BSLOT(0) + bofs;
        #pragma unroll
        for (int u = 0; u < 8; u++) cp16(bd + u * 16, bs + u * 4);
        CP_COMMIT();
        float4 v0 = *reinterpret_cast<const float4*>(A0 + (size_t)arow * 256 + aseg);
        float4 v1 = *reinterpret_cast<const float4*>(A0 + (size_t)arow * 256 + aseg + 4);
        sts_quad(sm, ASLOT(0) + (arow * AS + aseg) * 4, v0);
        sts_quad(sm, ASLOT(0) + (arow * AS + aseg + 4) * 4, v1);
    }

    for (int kc = 0; kc < 16; kc++) {
        CP_WAIT0();
        __syncthreads();
        const int cur = kc & 1, nxt = cur ^ 1;
        const bool pf = (kc < 15);

        float4 a0, a1;
        if (pf) {
            const float* Bn = ((kc + 1) < 8) ? B0 : B1;
            const int cb = ((kc + 1) & 7) * 32;
            const uint32_t bd = sbase + BSLOT(nxt) + bofs;
            const float* bs = Bn + (size_t)brow * 256 + cb;
            #pragma unroll
            for (int u = 0; u < 8; u++) cp16(bd + u * 16, bs + u * 4);
            CP_COMMIT();
            const float* An = ((kc + 1) < 8) ? A0 : A1;
            a0 = *reinterpret_cast<const float4*>(An + (size_t)arow * 256 + cb + aseg);
            a1 = *reinterpret_cast<const float4*>(An + (size_t)arow * 256 + cb + aseg + 4);
        }

        const uint32_t* Asp = reinterpret_cast<const uint32_t*>(sm + ASLOT(cur));
        const uint32_t* Bsp = reinterpret_cast<const uint32_t*>(sm + BSLOT(cur));
        mma_step(Asp, Bsp, acc, 0, g, c, rbase, nw);
        mma_step(Asp, Bsp, acc, 1, g, c, rbase, nw);
        mma_step(Asp, Bsp, acc, 2, g, c, rbase, nw);
        mma_step(Asp, Bsp, acc, 3, g, c, rbase, nw);

        if (pf) {
            sts_quad(sm, ASLOT(nxt) + (arow * AS + aseg) * 4, a0);
            sts_quad(sm, ASLOT(nxt) + (arow * AS + aseg + 4) * 4, a1);
        }
    }
}

#define ZERO_ACC() \
    _Pragma("unroll") for (int i = 0; i < 2; i++) \
    _Pragma("unroll") for (int j = 0; j < 8; j++) \
    _Pragma("unroll") for (int e = 0; e < 4; e++) acc[i][j][e] = 0.f

__global__ void round_weights_kernel(
    const float* __restrict__ Wa, const float* __restrict__ Ua,
    const float* __restrict__ Wh, const float* __restrict__ Uh,
    const float* __restrict__ Wz, const float* __restrict__ Uz)
{
    const float* src[6] = { Wa, Ua, Wh, Uh, Wz, Uz };
    const int m = blockIdx.y;
    const int i = blockIdx.x * blockDim.x + threadIdx.x;
    g_w[m * 65536 + i] = __uint_as_float(cvt_tf32(src[m][i]));
}

__global__ void __launch_bounds__(TPB, 2) gru_fused_kernel(
    const float* __restrict__ x, const float* __restrict__ hprev,
    const float* __restrict__ bz, const float* __restrict__ va,
    const float* __restrict__ bh, float* __restrict__ out)
{
    extern __shared__ char sm[];
    uint32_t sbase;
    asm("{ .reg .u64 t; cvta.to.shared.u64 t, %1; cvt.u32.u64 %0, t; }"
        : "=r"(sbase) : "l"(sm));
    const int tid = threadIdx.x;
    const int lane = tid & 31, w = tid >> 5;
    const int g = lane >> 2, c = lane & 3;
    const int mw = w & 1, nw = w >> 1;            // 2 M-tiles x 4 N-tiles
    const int rbase = mw * 32 + g;
    const int base = blockIdx.x * 64;

    const float* xb = x + (size_t)base * 256;
    const float* hb = hprev + (size_t)base * 256;
    float* attb = g_att + (size_t)base * 256;

    float acc[2][8][4];

    // =========== Phase 1: a_pre = x@Wa^T + h@Ua^T ===========
    ZERO_ACC();
    run_phase(sm, sbase, xb, hb, g_w, g_w + 65536, acc, tid, g, c, rbase, nw);

    // ---- Epilogue 1: s = tanh(a_pre)*va, row softmax, attended -> gmem ----
    {
        float* red = reinterpret_cast<float*>(sm + RED_OFF);
        float p[2][2][16];
        float mx[2][2], inv[2][2];

        #pragma unroll
        for (int i = 0; i < 2; i++)
            #pragma unroll
            for (int h = 0; h < 2; h++) {
                float m = -1e30f;
                #pragma unroll
                for (int j = 0; j < 8; j++)
                    #pragma unroll
                    for (int e = 0; e < 2; e++) {
                        const int col = nw * 64 + j * 8 + 2 * c + e;
                        float s = fast_tanh(acc[i][j][h * 2 + e]) * __ldg(&va[col]);
                        p[i][h][j * 2 + e] = s;
                        m = fmaxf(m, s);
                    }
                m = fmaxf(m, __shfl_xor_sync(0xffffffffu, m, 1));
                m = fmaxf(m, __shfl_xor_sync(0xffffffffu, m, 2));
                if (c == 0) red[(rbase + i * 16 + h * 8) * 4 + nw] = m;
            }
        __syncthreads();
        #pragma unroll
        for (int i = 0; i < 2; i++)
            #pragma unroll
            for (int h = 0; h < 2; h++) {
                const int row = rbase + i * 16 + h * 8;
                mx[i][h] = fmaxf(fmaxf(red[row * 4], red[row * 4 + 1]),
                                 fmaxf(red[row * 4 + 2], red[row * 4 + 3]));
            }
        __syncthreads();
        #pragma unroll
        for (int i = 0; i < 2; i++)
            #pragma unroll
            for (int h = 0; h < 2; h++) {
                float s = 0.f;
                #pragma unroll
                for (int k = 0; k < 16; k++) {
                    p[i][h][k] = __expf(p[i][h][k] - mx[i][h]);
                    s += p[i][h][k];
                }
                s += __shfl_xor_sync(0xffffffffu, s, 1);
                s += __shfl_xor_sync(0xffffffffu, s, 2);
                if (c == 0) red[(rbase + i * 16 + h * 8) * 4 + nw] = s;
            }
        __syncthreads();
        #pragma unroll
        for (int i = 0; i < 2; i++)
            #pragma unroll
            for (int h = 0; h < 2; h++) {
                const int row = rbase + i * 16 + h * 8;
                inv[i][h] = __frcp_rn(red[row * 4] + red[row * 4 + 1] +
                                      red[row * 4 + 2] + red[row * 4 + 3]);
            }
        #pragma unroll
        for (int i = 0; i < 2; i++)
            #pragma unroll
            for (int h = 0; h < 2; h++) {
                const int row = rbase + i * 16 + h * 8;
                const float2* hg = reinterpret_cast<const float2*>(hb + (size_t)row * 256);
                float2* ag = reinterpret_cast<float2*>(attb + (size_t)row * 256);
                #pragma unroll
                for (int j = 0; j < 8; j++) {
                    const int col = nw * 64 + j * 8 + 2 * c;
                    float2 hv = hg[col >> 1];
                    float2 av;
                    av.x = p[i][h][j * 2]     * inv[i][h] * hv.x;
                    av.y = p[i][h][j * 2 + 1] * inv[i][h] * hv.y;
                    ag[col >> 1] = av;
                }
            }
        __syncthreads();
    }

    // =========== Phase 2: h~_pre = x@Wh^T + attended@Uh^T ===========
    ZERO_ACC();
    run_phase(sm, sbase, xb, attb, g_w + 2 * 65536, g_w + 3 * 65536,
              acc, tid, g, c, rbase, nw);

    // ---- Epilogue 2: h~ = tanh(h~_pre + bh) -> gmem (overwrite attended) ----
    #pragma unroll
    for (int i = 0; i < 2; i++)
        #pragma unroll
        for (int h = 0; h < 2; h++) {
            const int row = rbase + i * 16 + h * 8;
            float2* ag = reinterpret_cast<float2*>(attb + (size_t)row * 256);
            #pragma unroll
            for (int j = 0; j < 8; j++) {
                const int col = nw * 64 + j * 8 + 2 * c;
                float2 t;
                t.x = fast_tanh(acc[i][j][h * 2]     + __ldg(&bh[col]));
                t.y = fast_tanh(acc[i][j][h * 2 + 1] + __ldg(&bh[col + 1]));
                ag[col >> 1] = t;
            }
        }
    __syncthreads();

    // =========== Phase 3: z_pre = x@Wz^T + h@Uz^T ===========
    ZERO_ACC();
    run_phase(sm, sbase, xb, hb, g_w + 4 * 65536, g_w + 5 * 65536,
              acc, tid, g, c, rbase, nw);

    // ---- Epilogue 3: z = sigmoid(z_pre + bz); out = (1-z)*h + z*h~ ----
    #pragma unroll
    for (int i = 0; i < 2; i++)
        #pragma unroll
        for (int h = 0; h < 2; h++) {
            const int row = rbase + i * 16 + h * 8;
            const float2* hg = reinterpret_cast<const float2*>(hb + (size_t)row * 256);
            const float2* tg = reinterpret_cast<const float2*>(attb + (size_t)row * 256);
            float2* og = reinterpret_cast<float2*>(out + (size_t)(base + row) * 256);
            #pragma unroll
            for (int j = 0; j < 8; j++) {
                const int col = nw * 64 + j * 8 + 2 * c;
                float2 hv = hg[col >> 1];
                float2 ht = tg[col >> 1];
                float z0 = fast_sig(acc[i][j][h * 2]     + __ldg(&bz[col]));
                float z1 = fast_sig(acc[i][j][h * 2 + 1] + __ldg(&bz[col + 1]));
                float2 o;
                o.x = (1.f - z0) * hv.x + z0 * ht.x;
                o.y = (1.f - z1) * hv.y + z1 * ht.y;
                og[col >> 1] = o;
            }
        }
}

extern "C" void kernel_launch(void* const* d_in, const int* in_sizes, int n_in,
                              void* d_out, int out_size) {
    const float* x  = (const float*)d_in[0];
    const float* h  = (const float*)d_in[1];
    const float* Wz = (const float*)d_in[2];
    const float* Uz = (const float*)d_in[3];
    const float* bz = (const float*)d_in[4];
    const float* Wa = (const float*)d_in[5];
    const float* Ua = (const float*)d_in[6];
    const float* va = (const float*)d_in[7];
    const float* Wh = (const float*)d_in[8];
    const float* Uh = (const float*)d_in[9];
    const float* bh = (const float*)d_in[10];
    float* out = (float*)d_out;

    const int B = in_sizes[0] / 256;   // 65536
    cudaFuncSetAttribute(gru_fused_kernel,
                         cudaFuncAttributeMaxDynamicSharedMemorySize, SMEM_TOTAL);
    round_weights_kernel<<<dim3(256, 6), 256>>>(Wa, Ua, Wh, Uh, Wz, Uz);
    gru_fused_kernel<<<B / 64, TPB, SMEM_TOTAL>>>(x, h, bz, va, bh, out);
}